// round 1
// baseline (speedup 1.0000x reference)
#include <cuda_runtime.h>
#include <cstdint>

// out[b,f] = -( sum_w x[b,w,f] * W[f,w] + bias[f] )
// x: [B=512, W=5, F=25000] f32   W: [F, 5] f32   bias: [F] f32   out: [B, F] f32
// Pure HBM-streaming kernel: float4-vectorized over f, W/bias hoisted to
// registers per block, 8 batch rows per block for W reuse, .cs streaming
// hints on x/out so L2 stays warm for W.

#define F_DIM   25000
#define WS      5
#define B_DIM   512
#define B_PER   8
#define NTHREADS 256
#define F4_DIM  (F_DIM / 4)   // 6250

__global__ __launch_bounds__(NTHREADS)
void ocsvm_kernel(const float* __restrict__ x,
                  const float* __restrict__ W,
                  const float* __restrict__ bias,
                  float* __restrict__ out) {
    const int f4 = blockIdx.x * NTHREADS + threadIdx.x;
    if (f4 >= F4_DIM) return;
    const int f = f4 * 4;

    // Hoist W[f..f+3][0..4] and bias into registers (reused across B_PER rows).
    float w[WS][4];
#pragma unroll
    for (int j = 0; j < 4; j++) {
#pragma unroll
        for (int wi = 0; wi < WS; wi++) {
            w[wi][j] = __ldg(&W[(size_t)(f + j) * WS + wi]);
        }
    }
    const float4 bb = *reinterpret_cast<const float4*>(bias + f);
    const float nb0 = -bb.x, nb1 = -bb.y, nb2 = -bb.z, nb3 = -bb.w;

    const int b0 = blockIdx.y * B_PER;

#pragma unroll
    for (int bi = 0; bi < B_PER; bi++) {
        const size_t base = (size_t)(b0 + bi) * (WS * F_DIM) + f;

        // Issue all 5 streaming loads up front (independent -> MLP=5).
        float4 xv[WS];
#pragma unroll
        for (int wi = 0; wi < WS; wi++) {
            xv[wi] = __ldcs(reinterpret_cast<const float4*>(x + base + (size_t)wi * F_DIM));
        }

        float a0 = nb0, a1 = nb1, a2 = nb2, a3 = nb3;
#pragma unroll
        for (int wi = 0; wi < WS; wi++) {
            a0 = fmaf(-xv[wi].x, w[wi][0], a0);
            a1 = fmaf(-xv[wi].y, w[wi][1], a1);
            a2 = fmaf(-xv[wi].z, w[wi][2], a2);
            a3 = fmaf(-xv[wi].w, w[wi][3], a3);
        }

        float4 o; o.x = a0; o.y = a1; o.z = a2; o.w = a3;
        __stcs(reinterpret_cast<float4*>(out + (size_t)(b0 + bi) * F_DIM + f), o);
    }
}

extern "C" void kernel_launch(void* const* d_in, const int* in_sizes, int n_in,
                              void* d_out, int out_size) {
    const float* x    = (const float*)d_in[0];
    const float* W    = (const float*)d_in[1];
    const float* bias = (const float*)d_in[2];
    float* out        = (float*)d_out;

    dim3 grid((F4_DIM + NTHREADS - 1) / NTHREADS,   // 25
              B_DIM / B_PER);                        // 64
    ocsvm_kernel<<<grid, NTHREADS>>>(x, W, bias, out);
}

// round 2
// speedup vs baseline: 1.0819x; 1.0819x over previous
#include <cuda_runtime.h>
#include <cstdint>

// out[b,f] = -( sum_w x[b,w,f] * W[f,w] + bias[f] )
// x: [512, 5, 25000] f32   W: [25000, 5] f32   bias: [25000] f32   out: [512, 25000] f32
//
// HBM-streaming kernel, R2: W/bias kept in a per-thread SMEM scratch column
// (conflict-free, bank = tid%32) instead of registers, freeing ~20 regs so
// occupancy rises from 4 to 6 CTAs/SM. B_PER reduced 8->4 for shorter blocks
// (smaller tail). x loads / out stores use .cs streaming hints.

#define F_DIM    25000
#define WS       5
#define B_DIM    512
#define B_PER    4
#define NTHREADS 256
#define F4_DIM   (F_DIM / 4)   // 6250

__global__ __launch_bounds__(NTHREADS, 6)
void ocsvm_kernel(const float* __restrict__ x,
                  const float* __restrict__ W,
                  const float* __restrict__ bias,
                  float* __restrict__ out) {
    // w_s[p][tid] holds W[(f + p/5)*5 + p%5] for this thread's 4 features.
    // Address stride across threads = 4B -> bank = tid%32: conflict-free.
    __shared__ float w_s[4 * WS][NTHREADS];

    const int tid = threadIdx.x;
    const int f4  = blockIdx.x * NTHREADS + tid;
    if (f4 >= F4_DIM) return;   // each thread only touches its own smem column
    const int f = f4 * 4;

    // This thread's 20 W floats are contiguous: W[f*5 .. f*5+20) = 5 x float4.
    {
        const float4* W4 = reinterpret_cast<const float4*>(W) + (size_t)f4 * WS;
#pragma unroll
        for (int k = 0; k < WS; k++) {
            float4 q = __ldg(W4 + k);
            w_s[4 * k + 0][tid] = q.x;
            w_s[4 * k + 1][tid] = q.y;
            w_s[4 * k + 2][tid] = q.z;
            w_s[4 * k + 3][tid] = q.w;
        }
    }
    const float4 bb = __ldg(reinterpret_cast<const float4*>(bias + f));
    const float nb0 = -bb.x, nb1 = -bb.y, nb2 = -bb.z, nb3 = -bb.w;

    const int b0 = blockIdx.y * B_PER;

#pragma unroll 1   // keep W reads in smem each iteration (don't re-hoist to regs)
    for (int bi = 0; bi < B_PER; bi++) {
        const size_t base = (size_t)(b0 + bi) * (WS * F_DIM) + f;

        // 5 independent streaming loads in flight.
        float4 xv[WS];
#pragma unroll
        for (int wi = 0; wi < WS; wi++) {
            xv[wi] = __ldcs(reinterpret_cast<const float4*>(x + base + (size_t)wi * F_DIM));
        }

        float a0 = nb0, a1 = nb1, a2 = nb2, a3 = nb3;
#pragma unroll
        for (int wi = 0; wi < WS; wi++) {
            a0 = fmaf(-xv[wi].x, w_s[0 * WS + wi][tid], a0);
            a1 = fmaf(-xv[wi].y, w_s[1 * WS + wi][tid], a1);
            a2 = fmaf(-xv[wi].z, w_s[2 * WS + wi][tid], a2);
            a3 = fmaf(-xv[wi].w, w_s[3 * WS + wi][tid], a3);
        }

        float4 o; o.x = a0; o.y = a1; o.z = a2; o.w = a3;
        __stcs(reinterpret_cast<float4*>(out + (size_t)(b0 + bi) * F_DIM + f), o);
    }
}

extern "C" void kernel_launch(void* const* d_in, const int* in_sizes, int n_in,
                              void* d_out, int out_size) {
    const float* x    = (const float*)d_in[0];
    const float* W    = (const float*)d_in[1];
    const float* bias = (const float*)d_in[2];
    float* out        = (float*)d_out;

    dim3 grid((F4_DIM + NTHREADS - 1) / NTHREADS,   // 25
              B_DIM / B_PER);                        // 128
    ocsvm_kernel<<<grid, NTHREADS>>>(x, W, bias, out);
}

// round 3
// speedup vs baseline: 1.1190x; 1.0343x over previous
#include <cuda_runtime.h>
#include <cstdint>

// out[b,f] = -( sum_w x[b,w,f] * W[f,w] + bias[f] )
// x: [512, 5, 25000] f32   W: [25000, 5] f32   bias: [25000] f32   out: [512, 25000] f32
//
// R3: B_PER 4->2 (6400 blocks, 7 waves over ~912 CTA slots) to shrink the
// partial-last-wave tail. W/bias live in a conflict-free per-thread SMEM
// column (bank = tid%32); x/out use .cs streaming hints; 5 independent
// LDG.128 in flight per batch row.

#define F_DIM    25000
#define WS       5
#define B_DIM    512
#define B_PER    2
#define NTHREADS 256
#define F4_DIM   (F_DIM / 4)   // 6250

__global__ __launch_bounds__(NTHREADS, 6)
void ocsvm_kernel(const float* __restrict__ x,
                  const float* __restrict__ W,
                  const float* __restrict__ bias,
                  float* __restrict__ out) {
    // w_s[p][tid] holds W[(f + p/5)*5 + p%5] for this thread's 4 features.
    // Per-thread column, 4B stride across threads -> bank = tid%32: conflict-free.
    __shared__ float w_s[4 * WS][NTHREADS];

    const int tid = threadIdx.x;
    const int f4  = blockIdx.x * NTHREADS + tid;
    if (f4 >= F4_DIM) return;   // each thread only touches its own smem column
    const int f = f4 * 4;

    // This thread's 20 W floats are contiguous: W[f*5 .. f*5+20) = 5 x float4.
    {
        const float4* W4 = reinterpret_cast<const float4*>(W) + (size_t)f4 * WS;
#pragma unroll
        for (int k = 0; k < WS; k++) {
            float4 q = __ldg(W4 + k);
            w_s[4 * k + 0][tid] = q.x;
            w_s[4 * k + 1][tid] = q.y;
            w_s[4 * k + 2][tid] = q.z;
            w_s[4 * k + 3][tid] = q.w;
        }
    }
    const float4 bb = __ldg(reinterpret_cast<const float4*>(bias + f));
    const float nb0 = -bb.x, nb1 = -bb.y, nb2 = -bb.z, nb3 = -bb.w;

    const int b0 = blockIdx.y * B_PER;

#pragma unroll 1   // keep W reads in smem each iteration (don't re-hoist to regs)
    for (int bi = 0; bi < B_PER; bi++) {
        const size_t base = (size_t)(b0 + bi) * (WS * F_DIM) + f;

        // 5 independent streaming loads in flight.
        float4 xv[WS];
#pragma unroll
        for (int wi = 0; wi < WS; wi++) {
            xv[wi] = __ldcs(reinterpret_cast<const float4*>(x + base + (size_t)wi * F_DIM));
        }

        float a0 = nb0, a1 = nb1, a2 = nb2, a3 = nb3;
#pragma unroll
        for (int wi = 0; wi < WS; wi++) {
            a0 = fmaf(-xv[wi].x, w_s[0 * WS + wi][tid], a0);
            a1 = fmaf(-xv[wi].y, w_s[1 * WS + wi][tid], a1);
            a2 = fmaf(-xv[wi].z, w_s[2 * WS + wi][tid], a2);
            a3 = fmaf(-xv[wi].w, w_s[3 * WS + wi][tid], a3);
        }

        float4 o; o.x = a0; o.y = a1; o.z = a2; o.w = a3;
        __stcs(reinterpret_cast<float4*>(out + (size_t)(b0 + bi) * F_DIM + f), o);
    }
}

extern "C" void kernel_launch(void* const* d_in, const int* in_sizes, int n_in,
                              void* d_out, int out_size) {
    const float* x    = (const float*)d_in[0];
    const float* W    = (const float*)d_in[1];
    const float* bias = (const float*)d_in[2];
    float* out        = (float*)d_out;

    dim3 grid((F4_DIM + NTHREADS - 1) / NTHREADS,   // 25
              B_DIM / B_PER);                        // 256
    ocsvm_kernel<<<grid, NTHREADS>>>(x, W, bias, out);
}